// round 3
// baseline (speedup 1.0000x reference)
#include <cuda_runtime.h>
#include <cstdint>

#define BATCH 4
#define CH    256
#define NPIX  4096
#define TQ    64
#define TJ    64
#define KST   260   // padded row stride (floats) for Qs/Ks/Vs
#define PST   68    // padded row stride for Ps
#define NTILE (NPIX / TJ)
#define NT    512

__device__ float g_Q[(size_t)BATCH * NPIX * CH];
__device__ float g_K[(size_t)BATCH * NPIX * CH];
__device__ float g_V[(size_t)BATCH * NPIX * CH];

// ---- Blackwell packed fp32x2 helpers -------------------------------------
__device__ __forceinline__ double ffma2(double a, double b, double c) {
    double d;
    asm("fma.rn.f32x2 %0, %1, %2, %3;" : "=d"(d) : "d"(a), "d"(b), "d"(c));
    return d;
}
__device__ __forceinline__ double pack2(float x) {
    double d;
    asm("mov.b64 %0, {%1, %1};" : "=d"(d) : "f"(x));
    return d;
}
__device__ __forceinline__ float2 unpack2(double d) {
    float2 r;
    asm("mov.b64 {%0, %1}, %2;" : "=f"(r.x), "=f"(r.y) : "d"(d));
    return r;
}
#define CP16(dst, src) asm volatile("cp.async.cg.shared.global [%0], [%1], 16;" :: "r"(dst), "l"(src))
#define CP_COMMIT()    asm volatile("cp.async.commit_group;")
#define CP_WAIT(n)     asm volatile("cp.async.wait_group %0;" :: "n"(n))

// ---------------------------------------------------------------------------
// Projection: out[b][p][o] = sum_c w[o][c] * x[b][c][p] + bias[o]
// ---------------------------------------------------------------------------
__global__ __launch_bounds__(256) void proj_kernel(
    const float* __restrict__ x, const float* __restrict__ w,
    const float* __restrict__ bias, int which)
{
    __shared__ float As[16][128];
    __shared__ float Bs[16 * 132];

    float* outp = (which == 0) ? g_Q : (which == 1) ? g_K : g_V;

    const int b  = blockIdx.z;
    const int p0 = blockIdx.x * 128;
    const int o0 = blockIdx.y * 128;
    const int t  = threadIdx.x;
    const int tx = t & 15;
    const int ty = t >> 4;

    float acc[8][8];
#pragma unroll
    for (int i = 0; i < 8; ++i)
#pragma unroll
        for (int j = 0; j < 8; ++j) acc[i][j] = 0.f;

    const float* xb = x + (size_t)b * CH * NPIX;

    const int lcc  = t >> 4;
    const int lcol = (t & 15) * 8;
    const int loo  = t >> 1;
    const int lch  = (t & 1) * 8;

    for (int c0 = 0; c0 < CH; c0 += 16) {
        {
            const float* src = xb + (size_t)(c0 + lcc) * NPIX + p0 + lcol;
            float4 v0 = *(const float4*)(src);
            float4 v1 = *(const float4*)(src + 4);
            *(float4*)&As[lcc][lcol]     = v0;
            *(float4*)&As[lcc][lcol + 4] = v1;
        }
        {
            const float* src = w + (size_t)(o0 + loo) * CH + c0 + lch;
            float4 v0 = *(const float4*)(src);
            float4 v1 = *(const float4*)(src + 4);
            Bs[(lch + 0) * 132 + loo] = v0.x;
            Bs[(lch + 1) * 132 + loo] = v0.y;
            Bs[(lch + 2) * 132 + loo] = v0.z;
            Bs[(lch + 3) * 132 + loo] = v0.w;
            Bs[(lch + 4) * 132 + loo] = v1.x;
            Bs[(lch + 5) * 132 + loo] = v1.y;
            Bs[(lch + 6) * 132 + loo] = v1.z;
            Bs[(lch + 7) * 132 + loo] = v1.w;
        }
        __syncthreads();
#pragma unroll
        for (int kk = 0; kk < 16; ++kk) {
            float a[8], bb[8];
            *(float4*)(a)      = *(float4*)&As[kk][ty * 8];
            *(float4*)(a + 4)  = *(float4*)&As[kk][ty * 8 + 4];
            *(float4*)(bb)     = *(float4*)&Bs[kk * 132 + tx * 8];
            *(float4*)(bb + 4) = *(float4*)&Bs[kk * 132 + tx * 8 + 4];
#pragma unroll
            for (int i = 0; i < 8; ++i)
#pragma unroll
                for (int j = 0; j < 8; ++j)
                    acc[i][j] += a[i] * bb[j];
        }
        __syncthreads();
    }

    float bv[8];
#pragma unroll
    for (int j = 0; j < 8; ++j) bv[j] = bias[o0 + tx * 8 + j];
#pragma unroll
    for (int i = 0; i < 8; ++i) {
        float* dst = outp + ((size_t)b * NPIX + p0 + ty * 8 + i) * CH + o0 + tx * 8;
        float4 r0 = make_float4(acc[i][0] + bv[0], acc[i][1] + bv[1],
                                acc[i][2] + bv[2], acc[i][3] + bv[3]);
        float4 r1 = make_float4(acc[i][4] + bv[4], acc[i][5] + bv[5],
                                acc[i][6] + bv[6], acc[i][7] + bv[7]);
        *(float4*)dst       = r0;
        *(float4*)(dst + 4) = r1;
    }
}

// ---------------------------------------------------------------------------
// Fused attention + LayerNorm. 512 threads, f32x2 math, cp.async pipeline.
// ---------------------------------------------------------------------------
__global__ __launch_bounds__(NT, 1) void attn_kernel(
    const float* __restrict__ lnw, const float* __restrict__ lnb,
    float* __restrict__ out)
{
    extern __shared__ float sm[];
    float* Qs = sm;                 // TQ * KST
    float* Ks = Qs + TQ * KST;      // TJ * KST
    float* Vs = Ks + TJ * KST;      // TJ * KST
    float* Ps = Vs + TJ * KST;      // TQ * PST

    const int b  = blockIdx.y;
    const int p0 = blockIdx.x * TQ;
    const int t  = threadIdx.x;

    const float* Qg = g_Q + ((size_t)b * NPIX + p0) * CH;
    const float* Kg = g_K + (size_t)b * NPIX * CH;
    const float* Vg = g_V + (size_t)b * NPIX * CH;

    const uint32_t Ks_a = (uint32_t)__cvta_generic_to_shared(Ks);
    const uint32_t Vs_a = (uint32_t)__cvta_generic_to_shared(Vs);

    // Load Q tile (plain), preload K0/V0 via cp.async
#pragma unroll
    for (int i = 0; i < 8; ++i) {
        int idx = t + NT * i, row = idx >> 6, c4 = (idx & 63) << 2;
        *(float4*)&Qs[row * KST + c4] = *(const float4*)(Qg + (size_t)row * CH + c4);
    }
#pragma unroll
    for (int i = 0; i < 8; ++i) {
        int idx = t + NT * i, row = idx >> 6, c4 = (idx & 63) << 2;
        CP16(Ks_a + (uint32_t)(row * KST + c4) * 4u, Kg + (size_t)row * CH + c4);
    }
    CP_COMMIT();
#pragma unroll
    for (int i = 0; i < 8; ++i) {
        int idx = t + NT * i, row = idx >> 6, c4 = (idx & 63) << 2;
        CP16(Vs_a + (uint32_t)(row * KST + c4) * 4u, Vg + (size_t)row * CH + c4);
    }
    CP_COMMIT();

    const int tq = t >> 4, tj = t & 15;          // S-stage thread grid 32x16
    const int qpart = t >> 5, cpart = t & 31;    // AV-stage thread grid 16x32
    const int cA = cpart * 4, cB = 128 + cpart * 4;

    double av[16];                               // O accum: 4q x (4 c-pairs)
#pragma unroll
    for (int i = 0; i < 16; ++i) av[i] = 0.0;

    for (int tile = 0; tile < NTILE; ++tile) {
        CP_WAIT(1);          // K(tile) complete (V(tile) may still fly)
        __syncthreads();

        // ---- S = Q K^T : 2q x 4j per thread, k paired into f32x2 lanes
        double s2[2][4];
#pragma unroll
        for (int i = 0; i < 2; ++i)
#pragma unroll
            for (int j = 0; j < 4; ++j) s2[i][j] = 0.0;

        const float* q0r = Qs + (2 * tq) * KST;
        const float* q1r = q0r + KST;
#pragma unroll 8
        for (int c4 = 0; c4 < 64; ++c4) {
            double2 qa = *(const double2*)(q0r + c4 * 4);
            double2 qb = *(const double2*)(q1r + c4 * 4);
#pragma unroll
            for (int jj = 0; jj < 4; ++jj) {
                double2 kv = *(const double2*)(Ks + (tj + 16 * jj) * KST + c4 * 4);
                s2[0][jj] = ffma2(qa.x, kv.x, s2[0][jj]);
                s2[0][jj] = ffma2(qa.y, kv.y, s2[0][jj]);
                s2[1][jj] = ffma2(qb.x, kv.x, s2[1][jj]);
                s2[1][jj] = ffma2(qb.y, kv.y, s2[1][jj]);
            }
        }

        // ---- softmax over the 64-key tile (complete per reference)
#pragma unroll
        for (int i = 0; i < 2; ++i) {
            float s[4];
#pragma unroll
            for (int j = 0; j < 4; ++j) { float2 u = unpack2(s2[i][j]); s[j] = u.x + u.y; }
            float mx = fmaxf(fmaxf(s[0], s[1]), fmaxf(s[2], s[3]));
#pragma unroll
            for (int off = 8; off > 0; off >>= 1)
                mx = fmaxf(mx, __shfl_xor_sync(0xffffffffu, mx, off, 16));
            float sum = 0.f, pv[4];
#pragma unroll
            for (int j = 0; j < 4; ++j) { pv[j] = __expf(s[j] - mx); sum += pv[j]; }
#pragma unroll
            for (int off = 8; off > 0; off >>= 1)
                sum += __shfl_xor_sync(0xffffffffu, sum, off, 16);
            const float inv = __fdividef(1.f, sum);
#pragma unroll
            for (int j = 0; j < 4; ++j)
                Ps[(2 * tq + i) * PST + tj + 16 * j] = pv[j] * inv;
        }

        CP_WAIT(0);          // V(tile) complete
        __syncthreads();     // Ks free; Vs + Ps visible to all

        if (tile < NTILE - 1) {   // K(t+1) load overlaps AV(t)
            const float* kb = Kg + (size_t)(tile + 1) * TJ * CH;
#pragma unroll
            for (int i = 0; i < 8; ++i) {
                int idx = t + NT * i, row = idx >> 6, c4 = (idx & 63) << 2;
                CP16(Ks_a + (uint32_t)(row * KST + c4) * 4u, kb + (size_t)row * CH + c4);
            }
            CP_COMMIT();
        }

        // ---- O += P V : 4q x 8c per thread, c paired into f32x2 lanes
        const float* prow = Ps + (qpart * 4) * PST;
#pragma unroll 2
        for (int j4 = 0; j4 < 16; ++j4) {
            float4 pv0 = *(const float4*)(prow + 0 * PST + j4 * 4);
            float4 pv1 = *(const float4*)(prow + 1 * PST + j4 * 4);
            float4 pv2 = *(const float4*)(prow + 2 * PST + j4 * 4);
            float4 pv3 = *(const float4*)(prow + 3 * PST + j4 * 4);
#pragma unroll
            for (int jj = 0; jj < 4; ++jj) {
                const float* vr = Vs + (j4 * 4 + jj) * KST;
                double2 va = *(const double2*)(vr + cA);
                double2 vb = *(const double2*)(vr + cB);
                double pd0 = pack2(((const float*)&pv0)[jj]);
                double pd1 = pack2(((const float*)&pv1)[jj]);
                double pd2 = pack2(((const float*)&pv2)[jj]);
                double pd3 = pack2(((const float*)&pv3)[jj]);
                av[0]  = ffma2(pd0, va.x, av[0]);
                av[1]  = ffma2(pd0, va.y, av[1]);
                av[2]  = ffma2(pd0, vb.x, av[2]);
                av[3]  = ffma2(pd0, vb.y, av[3]);
                av[4]  = ffma2(pd1, va.x, av[4]);
                av[5]  = ffma2(pd1, va.y, av[5]);
                av[6]  = ffma2(pd1, vb.x, av[6]);
                av[7]  = ffma2(pd1, vb.y, av[7]);
                av[8]  = ffma2(pd2, va.x, av[8]);
                av[9]  = ffma2(pd2, va.y, av[9]);
                av[10] = ffma2(pd2, vb.x, av[10]);
                av[11] = ffma2(pd2, vb.y, av[11]);
                av[12] = ffma2(pd3, va.x, av[12]);
                av[13] = ffma2(pd3, va.y, av[13]);
                av[14] = ffma2(pd3, vb.x, av[14]);
                av[15] = ffma2(pd3, vb.y, av[15]);
            }
        }
        __syncthreads();     // all threads done reading Vs

        if (tile < NTILE - 1) {   // V(t+1) load overlaps S(t+1)
            const float* vbg = Vg + (size_t)(tile + 1) * TJ * CH;
#pragma unroll
            for (int i = 0; i < 8; ++i) {
                int idx = t + NT * i, row = idx >> 6, c4 = (idx & 63) << 2;
                CP16(Vs_a + (uint32_t)(row * KST + c4) * 4u, vbg + (size_t)row * CH + c4);
            }
            CP_COMMIT();
        }
    }

    // ---- LayerNorm over channels (one query's 256 ch spread over 32 lanes)
    const float rn = 1.f / 256.f;
#pragma unroll
    for (int qq = 0; qq < 4; ++qq) {
        float o[8];
#pragma unroll
        for (int pp = 0; pp < 4; ++pp) {
            float2 u = unpack2(av[qq * 4 + pp]);
            o[pp * 2] = u.x; o[pp * 2 + 1] = u.y;
        }
        float s1 = 0.f, s2v = 0.f;
#pragma unroll
        for (int i = 0; i < 8; ++i) { s1 += o[i]; s2v += o[i] * o[i]; }
#pragma unroll
        for (int off = 16; off > 0; off >>= 1) {
            s1  += __shfl_xor_sync(0xffffffffu, s1, off);
            s2v += __shfl_xor_sync(0xffffffffu, s2v, off);
        }
        const float mean = s1 * rn;
        const float var  = s2v * rn - mean * mean;
        const float rstd = rsqrtf(var + 1e-5f);
        const int p = p0 + qpart * 4 + qq;
#pragma unroll
        for (int k = 0; k < 4; ++k) {
            int c = cA + k;      // o[0..3] = channels cA..cA+3 (va.x/va.y pairs)
            out[((size_t)b * CH + c) * NPIX + p] = (o[k] - mean) * rstd * lnw[c] + lnb[c];
            c = cB + k;          // o[4..7] = channels cB..cB+3
            out[((size_t)b * CH + c) * NPIX + p] = (o[4 + k] - mean) * rstd * lnw[c] + lnb[c];
        }
    }
}

// ---------------------------------------------------------------------------
extern "C" void kernel_launch(void* const* d_in, const int* in_sizes, int n_in,
                              void* d_out, int out_size)
{
    const float* x1  = (const float*)d_in[0];
    const float* x2  = (const float*)d_in[1];
    const float* qw  = (const float*)d_in[2];
    const float* qb  = (const float*)d_in[3];
    const float* kw  = (const float*)d_in[4];
    const float* kb  = (const float*)d_in[5];
    const float* vw  = (const float*)d_in[6];
    const float* vb  = (const float*)d_in[7];
    const float* lnw = (const float*)d_in[8];
    const float* lnb = (const float*)d_in[9];
    float* out = (float*)d_out;

    dim3 pg(NPIX / 128, CH / 128, BATCH);
    proj_kernel<<<pg, 256>>>(x1, qw, qb, 0);
    proj_kernel<<<pg, 256>>>(x2, kw, kb, 1);
    proj_kernel<<<pg, 256>>>(x2, vw, vb, 2);

    const int smem_bytes = (3 * TQ * KST + TQ * PST) * 4;  // 217088 B
    cudaFuncSetAttribute(attn_kernel, cudaFuncAttributeMaxDynamicSharedMemorySize,
                         smem_bytes);
    attn_kernel<<<dim3(NPIX / TQ, BATCH), NT, smem_bytes>>>(lnw, lnb, out);
}

// round 5
// speedup vs baseline: 2.8616x; 2.8616x over previous
#include <cuda_runtime.h>
#include <cuda_bf16.h>
#include <cstdint>

#define BATCH 4
#define CH    256
#define NPIX  4096
#define TQ    128
#define TJ    64
#define NTILE (NPIX / TJ)

__device__ __align__(128) __nv_bfloat16 g_Qh[(size_t)BATCH * NPIX * CH];
__device__ __align__(128) __nv_bfloat16 g_Ql[(size_t)BATCH * NPIX * CH];
__device__ __align__(128) __nv_bfloat16 g_Kh[(size_t)BATCH * NPIX * CH];
__device__ __align__(128) __nv_bfloat16 g_Kl[(size_t)BATCH * NPIX * CH];
__device__ __align__(128) __nv_bfloat16 g_Vh[(size_t)BATCH * CH * NPIX];  // channel-major
__device__ __align__(128) __nv_bfloat16 g_Vl[(size_t)BATCH * CH * NPIX];

// smem byte offsets (dynamic smem base)
#define SM_Q    0        // Qh 128 rows x 512B  (xor-swizzled)
#define SM_QL   65536    // Ql
#define SM_KH   131072   // Kh 64 x 512B   (stream buffer, reused by V)
#define SM_KL   163840   // Kl
#define SM_VH   131072   // Vh 256 x 128B
#define SM_VL   163840   // Vl
#define SM_PH   196608   // Ph 128 x 128B
#define SM_PL   212992   // Pl
#define SM_RED  229376   // 128 rows x 2 warps x float2 = 2048B
#define SM_TOT  231424

#define CP16(dst, src) asm volatile("cp.async.cg.shared.global [%0], [%1], 16;" :: "r"(dst), "l"(src))
#define CP_COMMIT()    asm volatile("cp.async.commit_group;")
#define CP_WAIT0()     asm volatile("cp.async.wait_group 0;")

__device__ __forceinline__ uint32_t smem_u32(const void* p) {
    uint32_t a;
    asm("{ .reg .u64 t; cvta.to.shared.u64 t, %1; cvt.u32.u64 %0, t; }" : "=r"(a) : "l"(p));
    return a;
}
__device__ __forceinline__ void ldsm4(uint32_t* r, uint32_t addr) {
    asm volatile("ldmatrix.sync.aligned.m8n8.x4.shared.b16 {%0,%1,%2,%3}, [%4];"
        : "=r"(r[0]), "=r"(r[1]), "=r"(r[2]), "=r"(r[3]) : "r"(addr));
}
__device__ __forceinline__ void mma16816(float* c, const uint32_t* a, uint32_t b0, uint32_t b1) {
    asm volatile(
        "mma.sync.aligned.m16n8k16.row.col.f32.bf16.bf16.f32 "
        "{%0,%1,%2,%3}, {%4,%5,%6,%7}, {%8,%9}, {%0,%1,%2,%3};"
        : "+f"(c[0]), "+f"(c[1]), "+f"(c[2]), "+f"(c[3])
        : "r"(a[0]), "r"(a[1]), "r"(a[2]), "r"(a[3]), "r"(b0), "r"(b1));
}
__device__ __forceinline__ uint32_t pack_bf(__nv_bfloat16 a, __nv_bfloat16 b) {
    uint16_t ra = *(uint16_t*)&a, rb = *(uint16_t*)&b;
    return (uint32_t)ra | ((uint32_t)rb << 16);
}
__device__ __forceinline__ void bsplit(float v, __nv_bfloat16& h, __nv_bfloat16& l) {
    h = __float2bfloat16(v);
    l = __float2bfloat16(v - __bfloat162float(h));
}

// ---------------------------------------------------------------------------
// Projection fp32 GEMM; epilogue emits bf16 hi/lo splits.
// which: 0=Q (token-major), 1=K (token-major), 2=V (channel-major)
// ---------------------------------------------------------------------------
__global__ __launch_bounds__(256) void proj_kernel(
    const float* __restrict__ x, const float* __restrict__ w,
    const float* __restrict__ bias, int which)
{
    __shared__ float As[16][128];
    __shared__ float Bs[16 * 132];

    const int b  = blockIdx.z;
    const int p0 = blockIdx.x * 128;
    const int o0 = blockIdx.y * 128;
    const int t  = threadIdx.x;
    const int tx = t & 15, ty = t >> 4;

    float acc[8][8];
#pragma unroll
    for (int i = 0; i < 8; ++i)
#pragma unroll
        for (int j = 0; j < 8; ++j) acc[i][j] = 0.f;

    const float* xb = x + (size_t)b * CH * NPIX;
    const int lcc = t >> 4, lcol = (t & 15) * 8, loo = t >> 1, lch = (t & 1) * 8;

    for (int c0 = 0; c0 < CH; c0 += 16) {
        {
            const float* src = xb + (size_t)(c0 + lcc) * NPIX + p0 + lcol;
            *(float4*)&As[lcc][lcol]     = *(const float4*)(src);
            *(float4*)&As[lcc][lcol + 4] = *(const float4*)(src + 4);
        }
        {
            const float* src = w + (size_t)(o0 + loo) * CH + c0 + lch;
            float4 v0 = *(const float4*)(src);
            float4 v1 = *(const float4*)(src + 4);
            Bs[(lch + 0) * 132 + loo] = v0.x; Bs[(lch + 1) * 132 + loo] = v0.y;
            Bs[(lch + 2) * 132 + loo] = v0.z; Bs[(lch + 3) * 132 + loo] = v0.w;
            Bs[(lch + 4) * 132 + loo] = v1.x; Bs[(lch + 5) * 132 + loo] = v1.y;
            Bs[(lch + 6) * 132 + loo] = v1.z; Bs[(lch + 7) * 132 + loo] = v1.w;
        }
        __syncthreads();
#pragma unroll
        for (int kk = 0; kk < 16; ++kk) {
            float a[8], bb[8];
            *(float4*)(a)      = *(float4*)&As[kk][ty * 8];
            *(float4*)(a + 4)  = *(float4*)&As[kk][ty * 8 + 4];
            *(float4*)(bb)     = *(float4*)&Bs[kk * 132 + tx * 8];
            *(float4*)(bb + 4) = *(float4*)&Bs[kk * 132 + tx * 8 + 4];
#pragma unroll
            for (int i = 0; i < 8; ++i)
#pragma unroll
                for (int j = 0; j < 8; ++j) acc[i][j] += a[i] * bb[j];
        }
        __syncthreads();
    }

    float bv[8];
#pragma unroll
    for (int j = 0; j < 8; ++j) bv[j] = bias[o0 + tx * 8 + j];

    if (which != 2) {
        __nv_bfloat16* oh = (which == 0) ? g_Qh : g_Kh;
        __nv_bfloat16* ol = (which == 0) ? g_Ql : g_Kl;
#pragma unroll
        for (int i = 0; i < 8; ++i) {
            uint32_t H[4], L[4];
#pragma unroll
            for (int jp = 0; jp < 4; ++jp) {
                __nv_bfloat16 h0, l0, h1, l1;
                bsplit(acc[i][jp * 2]     + bv[jp * 2],     h0, l0);
                bsplit(acc[i][jp * 2 + 1] + bv[jp * 2 + 1], h1, l1);
                H[jp] = pack_bf(h0, h1); L[jp] = pack_bf(l0, l1);
            }
            const size_t base = ((size_t)b * NPIX + p0 + ty * 8 + i) * CH + o0 + tx * 8;
            *(uint4*)(oh + base) = make_uint4(H[0], H[1], H[2], H[3]);
            *(uint4*)(ol + base) = make_uint4(L[0], L[1], L[2], L[3]);
        }
    } else {
#pragma unroll
        for (int j = 0; j < 8; ++j) {
            const int o = o0 + tx * 8 + j;
            uint32_t H[4], L[4];
#pragma unroll
            for (int ip = 0; ip < 4; ++ip) {
                __nv_bfloat16 h0, l0, h1, l1;
                bsplit(acc[ip * 2][j]     + bv[j], h0, l0);
                bsplit(acc[ip * 2 + 1][j] + bv[j], h1, l1);
                H[ip] = pack_bf(h0, h1); L[ip] = pack_bf(l0, l1);
            }
            const size_t base = ((size_t)b * CH + o) * NPIX + p0 + ty * 8;
            *(uint4*)(g_Vh + base) = make_uint4(H[0], H[1], H[2], H[3]);
            *(uint4*)(g_Vl + base) = make_uint4(L[0], L[1], L[2], L[3]);
        }
    }
}

// ---------------------------------------------------------------------------
// mma.sync attention + fused LayerNorm (bf16 2-term split, 3 MMAs/product)
// ---------------------------------------------------------------------------
__global__ __launch_bounds__(256, 1) void attn_kernel(
    const float* __restrict__ lnw, const float* __restrict__ lnb,
    float* __restrict__ out)
{
    extern __shared__ char smem[];
    const uint32_t sb = smem_u32(smem);
    const int t = threadIdx.x;
    const int lane = t & 31, wid = t >> 5;
    const int b = blockIdx.y;
    const int p0 = blockIdx.x * TQ;
    const int wq = wid >> 1, wh = wid & 1;      // wh = j-half (S) / c-half (AV)
    const int g = lane >> 2, tig = lane & 3;
    const uint32_t l15 = (uint32_t)(lane & 15), lhi = (uint32_t)(lane >> 4);

    // Q hi/lo -> smem (xor-swizzled, 512B rows)
    {
        const __nv_bfloat16* qh = g_Qh + ((size_t)b * NPIX + p0) * CH;
        const __nv_bfloat16* ql = g_Ql + ((size_t)b * NPIX + p0) * CH;
#pragma unroll
        for (int i = 0; i < 16; ++i) {
            int idx = t + 256 * i;
            int row = idx >> 5, c = idx & 31;
            uint32_t off = (uint32_t)row * 512u + (uint32_t)((c ^ (row & 7)) << 4);
            CP16(sb + SM_Q  + off, qh + (size_t)row * CH + c * 8);
            CP16(sb + SM_QL + off, ql + (size_t)row * CH + c * 8);
        }
        CP_COMMIT();
    }

    float oacc[2][16][4];
#pragma unroll
    for (int m = 0; m < 2; ++m)
#pragma unroll
        for (int nb = 0; nb < 16; ++nb)
#pragma unroll
            for (int i = 0; i < 4; ++i) oacc[m][nb][i] = 0.f;

    const uint32_t qrow = (uint32_t)(wq * 32) + l15;
    const uint32_t aQh = sb + SM_Q  + qrow * 512u;
    const uint32_t aQl = sb + SM_QL + qrow * 512u;
    const uint32_t qm7 = qrow & 7u;
    const uint32_t krow = (uint32_t)(wh * 32) + l15;
    const uint32_t aKh = sb + SM_KH + krow * 512u;
    const uint32_t aKl = sb + SM_KL + krow * 512u;
    const uint32_t km7 = krow & 7u;
    const uint32_t aPh = sb + SM_PH + qrow * 128u;
    const uint32_t aPl = sb + SM_PL + qrow * 128u;
    const uint32_t vrow = (uint32_t)(wh * 128) + l15;
    const uint32_t aVh = sb + SM_VH + vrow * 128u;
    const uint32_t aVl = sb + SM_VL + vrow * 128u;
    const uint32_t vm7 = vrow & 7u;

    const __nv_bfloat16* khb = g_Kh + (size_t)b * NPIX * CH;
    const __nv_bfloat16* klb = g_Kl + (size_t)b * NPIX * CH;
    const __nv_bfloat16* vhb = g_Vh + (size_t)b * CH * NPIX;
    const __nv_bfloat16* vlb = g_Vl + (size_t)b * CH * NPIX;

    float2* red = (float2*)(smem + SM_RED);

#pragma unroll 1
    for (int tile = 0; tile < NTILE; ++tile) {
        __syncthreads();   // prior AV done reading V buffer
        {
            const __nv_bfloat16* kh = khb + (size_t)tile * TJ * CH;
            const __nv_bfloat16* kl = klb + (size_t)tile * TJ * CH;
#pragma unroll
            for (int i = 0; i < 8; ++i) {
                int idx = t + 256 * i;
                int row = idx >> 5, c = idx & 31;
                uint32_t off = (uint32_t)row * 512u + (uint32_t)((c ^ (row & 7)) << 4);
                CP16(sb + SM_KH + off, kh + (size_t)row * CH + c * 8);
                CP16(sb + SM_KL + off, kl + (size_t)row * CH + c * 8);
            }
            CP_COMMIT();
        }
        CP_WAIT0();
        __syncthreads();

        // ---- S = Q K^T (warp tile 32q x 32j; 3-MMA split)
        float sacc[2][4][4];
#pragma unroll
        for (int m = 0; m < 2; ++m)
#pragma unroll
            for (int nb = 0; nb < 4; ++nb)
#pragma unroll
                for (int i = 0; i < 4; ++i) sacc[m][nb][i] = 0.f;

#pragma unroll
        for (int k = 0; k < 16; ++k) {
            const uint32_t kc = (uint32_t)(k * 2) + lhi;
            const uint32_t cq = (kc ^ qm7) << 4;
            const uint32_t ck = (kc ^ km7) << 4;
            uint32_t Ah[2][4], Al[2][4], Bh[2][4], Bl[2][4];
            ldsm4(Ah[0], aQh + cq); ldsm4(Ah[1], aQh + 8192u + cq);
            ldsm4(Al[0], aQl + cq); ldsm4(Al[1], aQl + 8192u + cq);
            ldsm4(Bh[0], aKh + ck); ldsm4(Bh[1], aKh + 8192u + ck);
            ldsm4(Bl[0], aKl + ck); ldsm4(Bl[1], aKl + 8192u + ck);
#pragma unroll
            for (int m = 0; m < 2; ++m)
#pragma unroll
                for (int nbp = 0; nbp < 2; ++nbp)
#pragma unroll
                    for (int h = 0; h < 2; ++h) {
                        float* c = sacc[m][nbp * 2 + h];
                        mma16816(c, Ah[m], Bh[nbp][h], Bh[nbp][h + 2]);
                        mma16816(c, Al[m], Bh[nbp][h], Bh[nbp][h + 2]);
                        mma16816(c, Ah[m], Bl[nbp][h], Bl[nbp][h + 2]);
                    }
        }

        // ---- softmax partials (exp stored back into sacc)
        float rmax[2][2];
#pragma unroll
        for (int m = 0; m < 2; ++m)
#pragma unroll
            for (int hf = 0; hf < 2; ++hf) {
                float mx = -1e30f;
#pragma unroll
                for (int nb = 0; nb < 4; ++nb) {
                    mx = fmaxf(mx, sacc[m][nb][hf * 2]);
                    mx = fmaxf(mx, sacc[m][nb][hf * 2 + 1]);
                }
                mx = fmaxf(mx, __shfl_xor_sync(0xffffffffu, mx, 1));
                mx = fmaxf(mx, __shfl_xor_sync(0xffffffffu, mx, 2));
                float s = 0.f;
#pragma unroll
                for (int nb = 0; nb < 4; ++nb)
#pragma unroll
                    for (int i2 = 0; i2 < 2; ++i2) {
                        float e = __expf(sacc[m][nb][hf * 2 + i2] - mx);
                        sacc[m][nb][hf * 2 + i2] = e;
                        s += e;
                    }
                s += __shfl_xor_sync(0xffffffffu, s, 1);
                s += __shfl_xor_sync(0xffffffffu, s, 2);
                rmax[m][hf] = mx;
                if (tig == 0) {
                    const int rowl = wq * 32 + m * 16 + g + hf * 8;
                    red[rowl * 2 + wh] = make_float2(mx, s);
                }
            }
        __syncthreads();   // K reads done, partials visible

        // ---- V^T loads into (now free) K buffers; overlap with combine
        {
            const __nv_bfloat16* vh = vhb + (size_t)tile * TJ;
            const __nv_bfloat16* vl = vlb + (size_t)tile * TJ;
#pragma unroll
            for (int i = 0; i < 8; ++i) {
                int idx = t + 256 * i;
                int row = idx >> 3, c = idx & 7;
                uint32_t off = (uint32_t)row * 128u + (uint32_t)((c ^ (row & 7)) << 4);
                CP16(sb + SM_VH + off, vh + (size_t)row * NPIX + c * 8);
                CP16(sb + SM_VL + off, vl + (size_t)row * NPIX + c * 8);
            }
            CP_COMMIT();
        }

        // ---- combine halves, normalize, split P to bf16 hi/lo in smem
#pragma unroll
        for (int m = 0; m < 2; ++m)
#pragma unroll
            for (int hf = 0; hf < 2; ++hf) {
                const int rowl = wq * 32 + m * 16 + g + hf * 8;
                float2 r0 = red[rowl * 2 + 0];
                float2 r1 = red[rowl * 2 + 1];
                float mx = fmaxf(r0.x, r1.x);
                float ssum = r0.y * __expf(r0.x - mx) + r1.y * __expf(r1.x - mx);
                float fac = __expf(rmax[m][hf] - mx) * __fdividef(1.f, ssum);
#pragma unroll
                for (int nb = 0; nb < 4; ++nb) {
                    float v0 = sacc[m][nb][hf * 2]     * fac;
                    float v1 = sacc[m][nb][hf * 2 + 1] * fac;
                    __nv_bfloat16 h0, l0, h1, l1;
                    bsplit(v0, h0, l0); bsplit(v1, h1, l1);
                    uint32_t chnk = ((uint32_t)(wh * 4 + nb)) ^ ((uint32_t)rowl & 7u);
                    uint32_t boff = (uint32_t)rowl * 128u + chnk * 16u + (uint32_t)tig * 4u;
                    *(uint32_t*)(smem + SM_PH + boff) = pack_bf(h0, h1);
                    *(uint32_t*)(smem + SM_PL + boff) = pack_bf(l0, l1);
                }
            }
        CP_WAIT0();
        __syncthreads();   // V + P visible

        // ---- O += P V (warp tile 32q x 128c; accumulate in registers)
#pragma unroll
        for (int kk = 0; kk < 4; ++kk) {
            const uint32_t kc = (uint32_t)(kk * 2) + lhi;
            const uint32_t cp_ = (kc ^ qm7) << 4;
            const uint32_t cv  = (kc ^ vm7) << 4;
            uint32_t Ph[2][4], Pl[2][4];
            ldsm4(Ph[0], aPh + cp_); ldsm4(Ph[1], aPh + 2048u + cp_);
            ldsm4(Pl[0], aPl + cp_); ldsm4(Pl[1], aPl + 2048u + cp_);
#pragma unroll
            for (int nbp = 0; nbp < 8; ++nbp) {
                uint32_t Bh[4], Bl[4];
                ldsm4(Bh, aVh + (uint32_t)nbp * 2048u + cv);
                ldsm4(Bl, aVl + (uint32_t)nbp * 2048u + cv);
#pragma unroll
                for (int m = 0; m < 2; ++m)
#pragma unroll
                    for (int h = 0; h < 2; ++h) {
                        float* c = oacc[m][nbp * 2 + h];
                        mma16816(c, Ph[m], Bh[h], Bh[h + 2]);
                        mma16816(c, Pl[m], Bh[h], Bh[h + 2]);
                        mma16816(c, Ph[m], Bl[h], Bl[h + 2]);
                    }
            }
        }
    }

    // ---- fused LayerNorm epilogue
    __syncthreads();
#pragma unroll
    for (int m = 0; m < 2; ++m)
#pragma unroll
        for (int hf = 0; hf < 2; ++hf) {
            const int rowl = wq * 32 + m * 16 + g + hf * 8;
            float s1 = 0.f, s2 = 0.f;
#pragma unroll
            for (int nb = 0; nb < 16; ++nb) {
                float v0 = oacc[m][nb][hf * 2], v1 = oacc[m][nb][hf * 2 + 1];
                s1 += v0 + v1; s2 += v0 * v0 + v1 * v1;
            }
            s1 += __shfl_xor_sync(0xffffffffu, s1, 1);
            s1 += __shfl_xor_sync(0xffffffffu, s1, 2);
            s2 += __shfl_xor_sync(0xffffffffu, s2, 1);
            s2 += __shfl_xor_sync(0xffffffffu, s2, 2);
            if (tig == 0) red[rowl * 2 + wh] = make_float2(s1, s2);
        }
    __syncthreads();
#pragma unroll
    for (int m = 0; m < 2; ++m)
#pragma unroll
        for (int hf = 0; hf < 2; ++hf) {
            const int rowl = wq * 32 + m * 16 + g + hf * 8;
            float2 r0 = red[rowl * 2], r1 = red[rowl * 2 + 1];
            const float mean = (r0.x + r1.x) * (1.f / 256.f);
            const float var  = (r0.y + r1.y) * (1.f / 256.f) - mean * mean;
            const float rstd = rsqrtf(var + 1e-5f);
            const int p = p0 + rowl;
#pragma unroll
            for (int nb = 0; nb < 16; ++nb)
#pragma unroll
                for (int i2 = 0; i2 < 2; ++i2) {
                    const int c = wh * 128 + nb * 8 + tig * 2 + i2;
                    out[((size_t)b * CH + c) * NPIX + p] =
                        (oacc[m][nb][hf * 2 + i2] - mean) * rstd * lnw[c] + lnb[c];
                }
        }
}

// ---------------------------------------------------------------------------
extern "C" void kernel_launch(void* const* d_in, const int* in_sizes, int n_in,
                              void* d_out, int out_size)
{
    const float* x1  = (const float*)d_in[0];
    const float* x2  = (const float*)d_in[1];
    const float* qw  = (const float*)d_in[2];
    const float* qb  = (const float*)d_in[3];
    const float* kw  = (const float*)d_in[4];
    const float* kb  = (const float*)d_in[5];
    const float* vw  = (const float*)d_in[6];
    const float* vb  = (const float*)d_in[7];
    const float* lnw = (const float*)d_in[8];
    const float* lnb = (const float*)d_in[9];
    float* out = (float*)d_out;

    dim3 pg(NPIX / 128, CH / 128, BATCH);
    proj_kernel<<<pg, 256>>>(x1, qw, qb, 0);
    proj_kernel<<<pg, 256>>>(x2, kw, kb, 1);
    proj_kernel<<<pg, 256>>>(x2, vw, vb, 2);

    cudaFuncSetAttribute(attn_kernel, cudaFuncAttributeMaxDynamicSharedMemorySize, SM_TOT);
    attn_kernel<<<dim3(NPIX / TQ, BATCH), 256, SM_TOT>>>(lnw, lnb, out);
}